// round 11
// baseline (speedup 1.0000x reference)
#include <cuda_runtime.h>
#include <cstddef>

// ---------------------------------------------------------------------------
// SSIM loss, fused single kernel (v4):
//   vertical blur packed over column pairs with f32x2 (FFMA2), streaming
//   11-deep circular window; horizontal blur + SSIM scalar; last block
//   finalizes. x,y: (48 planes) x 512 x 512 fp32. out[0] = 1 - mean(ssim).
// ---------------------------------------------------------------------------

#define IMG_H 512
#define IMG_W 512

#define TX 128
#define TY 16
#define RY 26            // TY + 10 rows with halo
#define RXF 140          // computed columns per block (70 pairs), even-aligned halo
#define RXP 140          // smem row stride (floats)
#define SMEM_V   (TY * RXP)            // 2240 floats per v-blurred array
#define SMEM_BYTES (5 * SMEM_V * 4)    // 44800 B -> 5 blocks/SM

// Gaussian taps, sigma=1.5, window=11.
#define G0 0.00102838f
#define G1 0.00759874f
#define G2 0.03600077f
#define G3 0.10936069f
#define G4 0.21300553f
#define G5 0.26601172f

typedef unsigned long long u64;

__device__ double g_accum;          // zero at load; reset by last block
__device__ unsigned int g_ticket;   // ditto

// ---- packed f32x2 helpers (Blackwell) -------------------------------------
static __device__ __forceinline__ u64 pk2(float v) {
    u64 r; asm("mov.b64 %0,{%1,%1};" : "=l"(r) : "f"(v)); return r;
}
static __device__ __forceinline__ u64 fma2(u64 a, u64 b, u64 c) {
    u64 d; asm("fma.rn.f32x2 %0,%1,%2,%3;" : "=l"(d) : "l"(a), "l"(b), "l"(c)); return d;
}
static __device__ __forceinline__ u64 mul2(u64 a, u64 b) {
    u64 d; asm("mul.rn.f32x2 %0,%1,%2;" : "=l"(d) : "l"(a), "l"(b)); return d;
}
static __device__ __forceinline__ u64 add2(u64 a, u64 b) {
    u64 d; asm("add.rn.f32x2 %0,%1,%2;" : "=l"(d) : "l"(a), "l"(b)); return d;
}

// Scalar 11-tap (immediate coefficients -> FFMA-imm, rt=1), static indices.
#define TAP11(dst, arr, off)                                   \
    do {                                                       \
        float _s = G0 * (arr)[(off) + 0];                      \
        _s = fmaf(G1, (arr)[(off) + 1], _s);                   \
        _s = fmaf(G2, (arr)[(off) + 2], _s);                   \
        _s = fmaf(G3, (arr)[(off) + 3], _s);                   \
        _s = fmaf(G4, (arr)[(off) + 4], _s);                   \
        _s = fmaf(G5, (arr)[(off) + 5], _s);                   \
        _s = fmaf(G4, (arr)[(off) + 6], _s);                   \
        _s = fmaf(G3, (arr)[(off) + 7], _s);                   \
        _s = fmaf(G2, (arr)[(off) + 8], _s);                   \
        _s = fmaf(G1, (arr)[(off) + 9], _s);                   \
        _s = fmaf(G0, (arr)[(off) + 10], _s);                  \
        (dst) = _s;                                            \
    } while (0)

__global__ void __launch_bounds__(256, 5)
ssim_fused_kernel(const float* __restrict__ x, const float* __restrict__ y,
                  float* __restrict__ out, float inv_n) {
    extern __shared__ float sm[];
    float* __restrict__ vp = sm;   // [5][TY][RXP]: mux, muy, xx, yy, xy

    const int tid   = threadIdx.x;
    const int plane = blockIdx.z;
    const int row0  = (int)blockIdx.y * TY - 5;
    const int lb    = (int)blockIdx.x * TX - 6;   // even: float2 loads aligned

    const float* __restrict__ xb = x + (size_t)plane * (IMG_H * IMG_W);
    const float* __restrict__ yb = y + (size_t)plane * (IMG_H * IMG_W);

    // ---- Phase AB: vertical blur, packed column pairs ---------------------
    // tasks 0..139: lin+sq for x (0..69) / y (70..139); 140..209: xy.
    // Column pair cp -> image cols (lb+2cp, lb+2cp+1): both in or both out.
    if (tid < 210) {
        u64 GP[6] = { pk2(G0), pk2(G1), pk2(G2), pk2(G3), pk2(G4), pk2(G5) };
        if (tid < 140) {
            const int  cp   = (tid < 70) ? tid : tid - 70;
            const int  qlin = (tid < 70) ? 0 : 1;
            const float* __restrict__ src = (tid < 70) ? xb : yb;
            const int  gc   = lb + 2 * cp;
            const bool inw  = (unsigned)gc < IMG_W;
            const float* __restrict__ colp = src + gc;

            u64 win[11];
#pragma unroll
            for (int r = 0; r < 10; ++r) {
                int gr = row0 + r;
                win[r] = (inw && (unsigned)gr < IMG_H)
                           ? __ldg((const u64*)(colp + gr * IMG_W)) : 0ull;
            }
            float* __restrict__ vl = vp + qlin * SMEM_V + 2 * cp;
            float* __restrict__ vs = vp + (qlin + 2) * SMEM_V + 2 * cp;
#pragma unroll
            for (int o = 0; o < TY; ++o) {
                int gr = row0 + o + 10;
                win[(o + 10) % 11] = (inw && (unsigned)gr < IMG_H)
                           ? __ldg((const u64*)(colp + gr * IMG_W)) : 0ull;
                u64 w0 = win[o % 11];
                u64 u  = mul2(GP[0], w0);
                u64 accL = u;
                u64 accS = mul2(u, w0);
#pragma unroll
                for (int k = 1; k <= 10; ++k) {
                    u64 w = win[(o + k) % 11];
                    u64 t = mul2(GP[k < 6 ? k : 10 - k], w);
                    accL = add2(accL, t);
                    accS = fma2(t, w, accS);
                }
                *(u64*)(vl + o * RXP) = accL;
                *(u64*)(vs + o * RXP) = accS;
            }
        } else {
            const int  cp  = tid - 140;
            const int  gc  = lb + 2 * cp;
            const bool inw = (unsigned)gc < IMG_W;
            const float* __restrict__ xc = xb + gc;
            const float* __restrict__ yc = yb + gc;

            u64 win[11];
#pragma unroll
            for (int r = 0; r < 10; ++r) {
                int gr = row0 + r;
                bool ok = inw && ((unsigned)gr < IMG_H);
                u64 a = ok ? __ldg((const u64*)(xc + gr * IMG_W)) : 0ull;
                u64 b = ok ? __ldg((const u64*)(yc + gr * IMG_W)) : 0ull;
                win[r] = mul2(a, b);
            }
            float* __restrict__ v4 = vp + 4 * SMEM_V + 2 * cp;
#pragma unroll
            for (int o = 0; o < TY; ++o) {
                int gr = row0 + o + 10;
                bool ok = inw && ((unsigned)gr < IMG_H);
                u64 a = ok ? __ldg((const u64*)(xc + gr * IMG_W)) : 0ull;
                u64 b = ok ? __ldg((const u64*)(yc + gr * IMG_W)) : 0ull;
                win[(o + 10) % 11] = mul2(a, b);
                u64 acc = mul2(GP[0], win[o % 11]);
#pragma unroll
                for (int k = 1; k <= 10; ++k)
                    acc = fma2(GP[k < 6 ? k : 10 - k], win[(o + k) % 11], acc);
                *(u64*)(v4 + o * RXP) = acc;
            }
        }
    }
    __syncthreads();

    // ---- Phase C: horizontal blur + SSIM (scalar, FFMA-imm) ---------------
    // Local col c corresponds to image col lb + c; output j needs cols
    // [j+1, j+11]. Task = (row, 4-col chunk): 512 tasks, 2 per thread.
    const float C1 = 1e-4f;   // (0.01*1)^2
    const float C2 = 9e-4f;   // (0.03*1)^2
    float lsum = 0.0f;

#pragma unroll
    for (int it = 0; it < 2; ++it) {
        int T   = it * 256 + tid;
        int row = T >> 5;
        int c0  = (T & 31) << 2;

        float res[5][4];
#pragma unroll
        for (int q = 0; q < 5; ++q) {
            const float* __restrict__ base = vp + q * SMEM_V + row * RXP + c0;
            float w[16];
#pragma unroll
            for (int k = 0; k < 4; ++k) {
                float4 t4 = *reinterpret_cast<const float4*>(base + 4 * k);
                w[4 * k + 0] = t4.x;
                w[4 * k + 1] = t4.y;
                w[4 * k + 2] = t4.z;
                w[4 * k + 3] = t4.w;
            }
#pragma unroll
            for (int j = 0; j < 4; ++j) TAP11(res[q][j], w, j + 1);
        }

#pragma unroll
        for (int j = 0; j < 4; ++j) {
            float mux  = res[0][j];
            float muy  = res[1][j];
            float mux2 = mux * mux;
            float muy2 = muy * muy;
            float muxy = mux * muy;
            float sx_  = res[2][j] - mux2;
            float sy_  = res[3][j] - muy2;
            float sxy_ = res[4][j] - muxy;
            float num = (2.0f * muxy + C1) * (2.0f * sxy_ + C2);
            float den = (mux2 + muy2 + C1) * (sx_ + sy_ + C2) + 1e-8f;
            lsum += __fdividef(num, den);
        }
    }

    // ---- Block reduce + global accumulate + last-block finalize -----------
#pragma unroll
    for (int o = 16; o; o >>= 1)
        lsum += __shfl_xor_sync(0xffffffffu, lsum, o);

    __shared__ float wsum[8];
    if ((tid & 31) == 0) wsum[tid >> 5] = lsum;
    __syncthreads();
    if (tid == 0) {
        float t = 0.0f;
#pragma unroll
        for (int i = 0; i < 8; ++i) t += wsum[i];
        atomicAdd(&g_accum, (double)t);
        __threadfence();
        unsigned int nb = gridDim.x * gridDim.y * gridDim.z;
        unsigned int tk = atomicAdd(&g_ticket, 1u);
        if (tk == nb - 1u) {
            double total = atomicAdd(&g_accum, 0.0);   // coherent L2 read
            out[0] = 1.0f - (float)(total * (double)inv_n);
            g_accum  = 0.0;     // reset for next graph replay
            g_ticket = 0u;
        }
    }
}

extern "C" void kernel_launch(void* const* d_in, const int* in_sizes, int n_in,
                              void* d_out, int out_size) {
    const float* x = (const float*)d_in[0];
    const float* y = (const float*)d_in[1];
    float* out = (float*)d_out;

    const int planes = in_sizes[0] / (IMG_H * IMG_W);   // 48
    const float inv_n = 1.0f / (float)in_sizes[0];

    dim3 grid(IMG_W / TX, IMG_H / TY, planes);   // 4 x 32 x 48 = 6144 blocks
    ssim_fused_kernel<<<grid, 256, SMEM_BYTES>>>(x, y, out, inv_n);
}

// round 12
// speedup vs baseline: 1.8592x; 1.8592x over previous
#include <cuda_runtime.h>
#include <cstddef>

// ---------------------------------------------------------------------------
// SSIM loss, fused single kernel (v5 = v3 + vectorized vertical blur):
//   Phase B: tasks = (group, col-pair, row-half); float2 LDG/STS, scalar
//   FFMA-imm taps. Phase C: horizontal blur + SSIM (unchanged from best).
//   x,y: (48 planes) x 512 x 512 fp32. out[0] = 1 - mean(ssim).
// ---------------------------------------------------------------------------

#define IMG_H 512
#define IMG_W 512

#define TX 128
#define TY 16
#define NPAIR 70         // column pairs per block: cols 0..139 (139 needed)
#define RXP 140          // smem row stride (floats)
#define SMEM_V   (TY * RXP)            // 2240 floats per v-blurred array
#define SMEM_BYTES (5 * SMEM_V * 4)    // 44800 B -> 5 blocks/SM

// Gaussian taps, sigma=1.5, window=11 (immediates -> FFMA-imm, rt=1).
#define G0 0.00102838f
#define G1 0.00759874f
#define G2 0.03600077f
#define G3 0.10936069f
#define G4 0.21300553f
#define G5 0.26601172f

__device__ double g_accum;          // zero at load; reset by last block
__device__ unsigned int g_ticket;   // ditto

// 11-tap weighted sum, static indices.
#define TAP11(dst, arr, off)                                   \
    do {                                                       \
        float _s = G0 * (arr)[(off) + 0];                      \
        _s = fmaf(G1, (arr)[(off) + 1], _s);                   \
        _s = fmaf(G2, (arr)[(off) + 2], _s);                   \
        _s = fmaf(G3, (arr)[(off) + 3], _s);                   \
        _s = fmaf(G4, (arr)[(off) + 4], _s);                   \
        _s = fmaf(G5, (arr)[(off) + 5], _s);                   \
        _s = fmaf(G4, (arr)[(off) + 6], _s);                   \
        _s = fmaf(G3, (arr)[(off) + 7], _s);                   \
        _s = fmaf(G2, (arr)[(off) + 8], _s);                   \
        _s = fmaf(G1, (arr)[(off) + 9], _s);                   \
        _s = fmaf(G0, (arr)[(off) + 10], _s);                  \
        (dst) = _s;                                            \
    } while (0)

__global__ void __launch_bounds__(256, 5)
ssim_fused_kernel(const float* __restrict__ x, const float* __restrict__ y,
                  float* __restrict__ out, float inv_n) {
    extern __shared__ float sm[];
    float* __restrict__ vp = sm;   // [5][TY][RXP]: mux, muy, xx, yy, xy

    const int tid   = threadIdx.x;
    const int plane = blockIdx.z;
    const int row0  = (int)blockIdx.y * TY - 5;
    const int lb    = (int)blockIdx.x * TX - 6;   // even: float2 never straddles edge

    const float* __restrict__ xb = x + (size_t)plane * (IMG_H * IMG_W);
    const float* __restrict__ yb = y + (size_t)plane * (IMG_H * IMG_W);

    // ---- Phase B: vertical blur, float2 column pairs, half-height tasks ---
    // 420 tasks: t/140 = group (0:x->mux,xx  1:y->muy,yy  2:xy->xy),
    // within group: pair = r%70, half = r/70. Window = 18 rows -> 8 outputs.
#pragma unroll
    for (int it = 0; it < 2; ++it) {
        const int t = tid + (it << 8);
        if (t >= 420) break;
        const int g    = t / 140;
        const int r    = t - g * 140;
        const int pair = (r < NPAIR) ? r : r - NPAIR;
        const int half = (r < NPAIR) ? 0 : 1;

        const int gc    = lb + 2 * pair;            // even; pair all-in or all-out
        const bool inw  = (unsigned)gc < IMG_W;
        const int rbase = row0 + half * 8;          // window rows rbase..rbase+17
        const int obase = half * 8;                 // output rows obase..obase+7

        float wx[18], wy[18];
        if (g == 2) {
            const float* __restrict__ xc = xb + gc;
            const float* __restrict__ yc = yb + gc;
#pragma unroll
            for (int i = 0; i < 18; ++i) {
                int gr = rbase + i;
                bool ok = inw && ((unsigned)gr < IMG_H);
                float2 a = ok ? __ldg((const float2*)(xc + gr * IMG_W))
                              : make_float2(0.f, 0.f);
                float2 b = ok ? __ldg((const float2*)(yc + gr * IMG_W))
                              : make_float2(0.f, 0.f);
                wx[i] = a.x * b.x;
                wy[i] = a.y * b.y;
            }
            float* __restrict__ v4 = vp + 4 * SMEM_V + obase * RXP + 2 * pair;
#pragma unroll
            for (int o = 0; o < 8; ++o) {
                float sxv, syv;
                TAP11(sxv, wx, o);
                TAP11(syv, wy, o);
                *(float2*)(v4 + o * RXP) = make_float2(sxv, syv);
            }
        } else {
            const float* __restrict__ src = g ? (yb + gc) : (xb + gc);
#pragma unroll
            for (int i = 0; i < 18; ++i) {
                int gr = rbase + i;
                bool ok = inw && ((unsigned)gr < IMG_H);
                float2 a = ok ? __ldg((const float2*)(src + gr * IMG_W))
                              : make_float2(0.f, 0.f);
                wx[i] = a.x;
                wy[i] = a.y;
            }
            float* __restrict__ vl = vp + g * SMEM_V + obase * RXP + 2 * pair;
#pragma unroll
            for (int o = 0; o < 8; ++o) {
                float sxv, syv;
                TAP11(sxv, wx, o);
                TAP11(syv, wy, o);
                *(float2*)(vl + o * RXP) = make_float2(sxv, syv);
            }
#pragma unroll
            for (int i = 0; i < 18; ++i) { wx[i] *= wx[i]; wy[i] *= wy[i]; }
            float* __restrict__ vs = vp + (2 + g) * SMEM_V + obase * RXP + 2 * pair;
#pragma unroll
            for (int o = 0; o < 8; ++o) {
                float sxv, syv;
                TAP11(sxv, wx, o);
                TAP11(syv, wy, o);
                *(float2*)(vs + o * RXP) = make_float2(sxv, syv);
            }
        }
    }
    __syncthreads();

    // ---- Phase C: horizontal blur + SSIM (identical to 86.5us version) ----
    // Local col c <-> image col lb + c; output j of chunk c0 reads cols
    // [c0+j+1, c0+j+11] (center c0+j+6 -> image col 128*bx + c0 + j).
    const float C1 = 1e-4f;   // (0.01*1)^2
    const float C2 = 9e-4f;   // (0.03*1)^2
    float lsum = 0.0f;

#pragma unroll
    for (int it = 0; it < 2; ++it) {
        int T   = it * 256 + tid;
        int row = T >> 5;
        int c0  = (T & 31) << 2;

        float res[5][4];
#pragma unroll
        for (int q = 0; q < 5; ++q) {
            const float* __restrict__ base = vp + q * SMEM_V + row * RXP + c0;
            float w[16];
#pragma unroll
            for (int k = 0; k < 4; ++k) {
                float4 t4 = *reinterpret_cast<const float4*>(base + 4 * k);
                w[4 * k + 0] = t4.x;
                w[4 * k + 1] = t4.y;
                w[4 * k + 2] = t4.z;
                w[4 * k + 3] = t4.w;
            }
#pragma unroll
            for (int j = 0; j < 4; ++j) TAP11(res[q][j], w, j + 1);
        }

#pragma unroll
        for (int j = 0; j < 4; ++j) {
            float mux  = res[0][j];
            float muy  = res[1][j];
            float mux2 = mux * mux;
            float muy2 = muy * muy;
            float muxy = mux * muy;
            float sx_  = res[2][j] - mux2;
            float sy_  = res[3][j] - muy2;
            float sxy_ = res[4][j] - muxy;
            float num = (2.0f * muxy + C1) * (2.0f * sxy_ + C2);
            float den = (mux2 + muy2 + C1) * (sx_ + sy_ + C2) + 1e-8f;
            lsum += __fdividef(num, den);
        }
    }

    // ---- Block reduce + global accumulate + last-block finalize -----------
#pragma unroll
    for (int o = 16; o; o >>= 1)
        lsum += __shfl_xor_sync(0xffffffffu, lsum, o);

    __shared__ float wsum[8];
    if ((tid & 31) == 0) wsum[tid >> 5] = lsum;
    __syncthreads();
    if (tid == 0) {
        float t = 0.0f;
#pragma unroll
        for (int i = 0; i < 8; ++i) t += wsum[i];
        atomicAdd(&g_accum, (double)t);
        __threadfence();
        unsigned int nb = gridDim.x * gridDim.y * gridDim.z;
        unsigned int tk = atomicAdd(&g_ticket, 1u);
        if (tk == nb - 1u) {
            double total = atomicAdd(&g_accum, 0.0);   // coherent L2 read
            out[0] = 1.0f - (float)(total * (double)inv_n);
            g_accum  = 0.0;     // reset for next graph replay
            g_ticket = 0u;
        }
    }
}

extern "C" void kernel_launch(void* const* d_in, const int* in_sizes, int n_in,
                              void* d_out, int out_size) {
    const float* x = (const float*)d_in[0];
    const float* y = (const float*)d_in[1];
    float* out = (float*)d_out;

    const int planes = in_sizes[0] / (IMG_H * IMG_W);   // 48
    const float inv_n = 1.0f / (float)in_sizes[0];

    dim3 grid(IMG_W / TX, IMG_H / TY, planes);   // 4 x 32 x 48 = 6144 blocks
    ssim_fused_kernel<<<grid, 256, SMEM_BYTES>>>(x, y, out, inv_n);
}